// round 4
// baseline (speedup 1.0000x reference)
#include <cuda_runtime.h>

#define N_ATOMS 100000
#define N_PAIRS 3200000
#define NT4     (N_PAIRS / 4)   // 800000, exact
#define ZMAX    96
#define NBLK    148              // one persistent CTA per SM
#define NTHR    1024
#define SMEM_BYTES (N_ATOMS + ZMAX * 4)   // 100384 bytes dynamic smem

// Scratch (no allocation allowed)
__device__ __align__(16) unsigned char g_z8[N_ATOMS];  // Z in [1,95), 100KB
__device__ float  g_zpow[ZMAX];                        // z^|a_exponent| LUT
__device__ float4 g_params4[3];                        // [0]=c  [1]=e  [2]={inv_a,K,-,-}

__global__ void __launch_bounds__(256) prep_kernel(
    const int* __restrict__ Z,
    const float* __restrict__ a_coef, const float* __restrict__ a_exp,
    const float* __restrict__ phi_c,  const float* __restrict__ phi_e,
    const float* __restrict__ ke,     const float* __restrict__ d2A,
    const float* __restrict__ e2m,
    float* __restrict__ out)
{
    int n = blockIdx.x * blockDim.x + threadIdx.x;
    if (n == 0) {
        float a0 = fabsf(phi_c[0]), a1 = fabsf(phi_c[1]),
              a2 = fabsf(phi_c[2]), a3 = fabsf(phi_c[3]);
        float inv_s = 1.0f / (a0 + a1 + a2 + a3);
        g_params4[0] = make_float4(a0 * inv_s, a1 * inv_s, a2 * inv_s, a3 * inv_s);
        g_params4[1] = make_float4(fabsf(phi_e[0]), fabsf(phi_e[1]),
                                   fabsf(phi_e[2]), fabsf(phi_e[3]));
        g_params4[2] = make_float4(1.0f / fabsf(a_coef[0]),
                                   ke[0] * e2m[0] / d2A[0], 0.0f, 0.0f);
    }
    if (n < ZMAX) {
        g_zpow[n] = __powf((float)n, fabsf(a_exp[0]));   // n=0 unused
    }
    if (n < N_ATOMS) {
        g_z8[n] = (unsigned char)Z[n];
        out[n] = 0.0f;                     // d_out poisoned -> zero it
    }
}

__device__ __forceinline__ float pair_val(
    float d, float ct, int zi, int zj, const float* __restrict__ s_zpow,
    float4 C, float4 E, float inv_a, float K)
{
    float za  = s_zpow[zi] + s_zpow[zj];
    float arg = d * za * inv_a;
    float phi = C.x * __expf(-E.x * arg)
              + C.y * __expf(-E.y * arg)
              + C.z * __expf(-E.z * arg)
              + C.w * __expf(-E.w * arg);
    float zz = (float)zi * (float)zj;
    return K * zz * phi * ct * __fdividef(1.0f, d);
}

__global__ void __launch_bounds__(NTHR) pair_kernel(
    const float4* __restrict__ dist, const float4* __restrict__ cut,
    const int4*  __restrict__ idx_i, const int4*  __restrict__ idx_j,
    float* __restrict__ out)
{
    extern __shared__ unsigned char smem[];
    unsigned char* s_z8   = smem;
    float*         s_zpow = (float*)(smem + N_ATOMS);   // N_ATOMS % 16 == 0

    // Stage the 100KB atomic-number table into smem (int4 copies, L2-resident)
    {
        const int4* src = (const int4*)g_z8;
        int4*       dst = (int4*)s_z8;
        #pragma unroll 4
        for (int i = threadIdx.x; i < N_ATOMS / 16; i += NTHR) dst[i] = src[i];
        if (threadIdx.x < ZMAX) s_zpow[threadIdx.x] = g_zpow[threadIdx.x];
    }
    __syncthreads();

    float4 C  = g_params4[0];
    float4 E  = g_params4[1];
    float4 P2 = g_params4[2];
    float inv_a = P2.x, K = P2.y;

    const unsigned m = 0xffffffffu;
    int lane = threadIdx.x & 31;
    unsigned mask_le = 0xffffffffu >> (31 - lane);

    for (int t = blockIdx.x * NTHR + threadIdx.x; t < NT4; t += NBLK * NTHR) {
        int4   si = idx_i[t];
        int4   sj = idx_j[t];
        float4 d  = dist[t];
        float4 ct = cut[t];

        // smem gathers: random byte loads, low bank-conflict degree
        int zi0 = s_z8[si.x], zi1 = s_z8[si.y], zi2 = s_z8[si.z], zi3 = s_z8[si.w];
        int zj0 = s_z8[sj.x], zj1 = s_z8[sj.y], zj2 = s_z8[sj.z], zj3 = s_z8[sj.w];

        float v0 = pair_val(d.x, ct.x, zi0, zj0, s_zpow, C, E, inv_a, K);
        float v1 = pair_val(d.y, ct.y, zi1, zj1, s_zpow, C, E, inv_a, K);
        float v2 = pair_val(d.z, ct.z, zi2, zj2, s_zpow, C, E, inv_a, K);
        float v3 = pair_val(d.w, ct.w, zi3, zj3, s_zpow, C, E, inv_a, K);

        // In-thread serial segmented combine (idx_i sorted; boundaries rare)
        int   seg = si.x;
        float acc = v0;
        if (si.y == seg) acc += v1; else { atomicAdd(&out[seg], acc); seg = si.y; acc = v1; }
        if (si.z == seg) acc += v2; else { atomicAdd(&out[seg], acc); seg = si.z; acc = v2; }
        if (si.w == seg) acc += v3; else { atomicAdd(&out[seg], acc); seg = si.w; acc = v3; }

        // Warp segmented inclusive scan over (seg, acc)
        int segp = __shfl_up_sync(m, seg, 1);
        bool head = (lane == 0) || (segp != seg);
        unsigned hb = __ballot_sync(m, head);
        int head_lane = 31 - __clz(hb & mask_le);
        #pragma unroll
        for (int off = 1; off < 32; off <<= 1) {
            float vv = __shfl_up_sync(m, acc, off);
            if (lane - off >= head_lane) acc += vv;
        }
        unsigned tails = (hb >> 1) | 0x80000000u;  // tail(k) = head(k+1) or k==31
        if ((tails >> lane) & 1) {
            atomicAdd(&out[seg], acc);
        }
    }
}

extern "C" void kernel_launch(void* const* d_in, const int* in_sizes, int n_in,
                              void* d_out, int out_size)
{
    const int*   Z    = (const int*)  d_in[0];
    const float* dist = (const float*)d_in[1];
    const float* cutv = (const float*)d_in[2];
    const int*   ii   = (const int*)  d_in[3];
    const int*   jj   = (const int*)  d_in[4];
    const float* ac   = (const float*)d_in[5];
    const float* ae   = (const float*)d_in[6];
    const float* pc   = (const float*)d_in[7];
    const float* pe   = (const float*)d_in[8];
    const float* ke   = (const float*)d_in[9];
    const float* d2A  = (const float*)d_in[10];
    const float* e2m  = (const float*)d_in[11];
    float* out = (float*)d_out;

    cudaFuncSetAttribute(pair_kernel,
                         cudaFuncAttributeMaxDynamicSharedMemorySize, SMEM_BYTES);

    prep_kernel<<<(N_ATOMS + 255) / 256, 256>>>(Z, ac, ae, pc, pe, ke, d2A, e2m, out);
    pair_kernel<<<NBLK, NTHR, SMEM_BYTES>>>(
        (const float4*)dist, (const float4*)cutv,
        (const int4*)ii, (const int4*)jj, out);
}